// round 11
// baseline (speedup 1.0000x reference)
#include <cuda_runtime.h>

// Problem constants (fixed by the reference)
#define NN 50000          // nodes
#define NE 800000         // edges
#define DD 96             // feature dim
#define D4 24             // DD / 4 (float4 groups)

// ---------------- scratch (device globals; no allocation allowed) ----------
__device__ float g_x[NN * DD];     // ping buffer (layer 0 output)
__device__ float g_y[NN * DD];     // pong buffer (layer 1 output)
__device__ int   g_od[NN];         // out degree (src side)
__device__ int   g_id[NN];         // in degree (dst side)
__device__ float g_ns[NN];         // out_deg^-1/2
__device__ float g_nd[NN];         // in_deg^-1/2
__device__ int   g_off[NN + 1];    // CSR offsets (by dst)
__device__ int   g_cur[NN];        // CSR fill cursors
__device__ int   g_eidx[NE];       // src ids grouped by dst
__device__ int   g_is64;           // 1 if index arrays are int64, 0 if int32

__device__ __forceinline__ int load_idx(const void* p, int e, int is64) {
    if (is64) return (int)((const long long*)p)[e];
    return ((const int*)p)[e];
}

// ---------------- init: zero degrees everywhere + dtype probe in block 0 ----
// int32 ids read as int64 pack two ids per word -> value >= 2^32 unless the
// high id is 0 (prob 1/50000 per sample; 256 samples -> certain detection).
__global__ void k_init(const void* src, const void* dst) {
    int i = blockIdx.x * blockDim.x + threadIdx.x;
    if (i < NN) { g_od[i] = 0; g_id[i] = 0; }
    if (blockIdx.x == 0) {
        __shared__ int bad;
        if (threadIdx.x == 0) bad = 0;
        __syncthreads();
        long long v1 = ((const long long*)src)[threadIdx.x];
        long long v2 = ((const long long*)dst)[threadIdx.x];
        if (v1 < 0 || v1 >= NN || v2 < 0 || v2 >= NN) bad = 1;
        __syncthreads();
        if (threadIdx.x == 0) g_is64 = bad ? 0 : 1;
    }
}

__global__ void k_deg(const void* __restrict__ src, const void* __restrict__ dst) {
    int e = blockIdx.x * blockDim.x + threadIdx.x;
    if (e < NE) {
        int is64 = g_is64;
        atomicAdd(&g_od[load_idx(src, e, is64)], 1);
        atomicAdd(&g_id[load_idx(dst, e, is64)], 1);
    }
}

// ---------------- norms + exclusive scan of in-degrees (single block) -------
#define SCAN_T 1024
#define CHUNK 49   // 1024*49 = 50176 >= NN
__global__ void k_norm_scan() {
    int t = threadIdx.x;
    int s0 = t * CHUNK;
    int sum = 0;
    for (int i = 0; i < CHUNK; i++) {
        int n = s0 + i;
        if (n < NN) {
            int idg = g_id[n];
            g_ns[n] = rsqrtf((float)max(g_od[n], 1));
            g_nd[n] = rsqrtf((float)max(idg, 1));
            sum += idg;
        }
    }
    __shared__ int wsum[32];
    int lane = t & 31, wid = t >> 5;
    int v = sum;
    for (int o = 1; o < 32; o <<= 1) {
        int u = __shfl_up_sync(0xffffffffu, v, o);
        if (lane >= o) v += u;
    }
    if (lane == 31) wsum[wid] = v;
    __syncthreads();
    if (wid == 0) {
        int w = wsum[lane];
        for (int o = 1; o < 32; o <<= 1) {
            int u = __shfl_up_sync(0xffffffffu, w, o);
            if (lane >= o) w += u;
        }
        wsum[lane] = w;
    }
    __syncthreads();
    int run = v - sum + (wid > 0 ? wsum[wid - 1] : 0);  // exclusive prefix
    for (int i = 0; i < CHUNK; i++) {
        int n = s0 + i;
        if (n < NN) {
            g_off[n] = run;
            g_cur[n] = run;
            run += g_id[n];
        }
    }
    if (t == SCAN_T - 1) g_off[NN] = run;  // == NE
}

__global__ void k_fill(const void* __restrict__ src, const void* __restrict__ dst) {
    int e = blockIdx.x * blockDim.x + threadIdx.x;
    if (e < NE) {
        int is64 = g_is64;
        int s = load_idx(src, e, is64);
        int d = load_idx(dst, e, is64);
        int pos = atomicAdd(&g_cur[d], 1);
        g_eidx[pos] = s;
    }
}

// ---------------- fused layer: CSR gather -> smem -> GEMM + bias + relu -----
// Block = 192 threads, tile = 32 dst nodes. IMPORTANT: X (input) and out
// (output) must be DISJOINT buffers — the gather phase of one block runs
// concurrently with the epilogue of others.
// Phase 1: 6 warps gather node messages straight into Ms (no g_m round-trip).
//   SCALE_EDGE=1 (layer 0): X is raw h; scale each message by g_ns[src] via
//   shuffle-broadcast FMA. SCALE_EDGE=0: X is pre-scaled by prior epilogue.
// Phase 2: 32x96 GEMM from smem (4x4 register tiles), bias+relu epilogue.
//   SCALE_OUT=1: multiply output by norm_src (pre-scale for next layer).
template <int SCALE_EDGE, int SCALE_OUT>
__global__ __launch_bounds__(192) void k_layer(const float* __restrict__ X,
                                               const float* __restrict__ W,
                                               const float* __restrict__ B,
                                               float* __restrict__ out) {
    __shared__ float Ws[DD * DD];   // 36864 B
    __shared__ float Ms[32 * DD];   // 12288 B  (48KB total)
    int tid = threadIdx.x;
    int warp = tid >> 5;
    int lane = tid & 31;
    int row0 = blockIdx.x * 32;

    // Kick off W loads first: independent LDGs whose latency hides under gather.
    const float4* W4 = (const float4*)W;
    float4 wld[12];
#pragma unroll
    for (int i = 0; i < 12; i++) wld[i] = W4[tid + i * 192];

    // Gather phase: warp w handles tile rows {w, w+6, w+12, ...}
    for (int nl = warp; nl < 32; nl += 6) {
        int node = row0 + nl;
        float a0 = 0.f, a1 = 0.f, a2 = 0.f;
        if (node < NN) {
            int beg = g_off[node];
            int end = g_off[node + 1];
            for (int base = beg; base < end; base += 32) {
                int got = min(32, end - base);
                int idx = (base + lane < end) ? g_eidx[base + lane] : 0;
                float nsv = 0.f;
                if (SCALE_EDGE) nsv = (base + lane < end) ? g_ns[idx] : 0.f;
#pragma unroll 4
                for (int j = 0; j < got; j++) {
                    int s = __shfl_sync(0xffffffffu, idx, j);
                    const float* xp = X + s * DD;
                    if (SCALE_EDGE) {
                        float f = __shfl_sync(0xffffffffu, nsv, j);
                        a0 = fmaf(xp[lane],      f, a0);
                        a1 = fmaf(xp[lane + 32], f, a1);
                        a2 = fmaf(xp[lane + 64], f, a2);
                    } else {
                        a0 += xp[lane];
                        a1 += xp[lane + 32];
                        a2 += xp[lane + 64];
                    }
                }
            }
            float nd = g_nd[node];
            a0 *= nd; a1 *= nd; a2 *= nd;
        }
        Ms[nl * DD + lane]      = a0;
        Ms[nl * DD + lane + 32] = a1;
        Ms[nl * DD + lane + 64] = a2;
    }

    // Stash W into smem
    float4* Ws4 = (float4*)Ws;
#pragma unroll
    for (int i = 0; i < 12; i++) Ws4[tid + i * 192] = wld[i];
    __syncthreads();

    // GEMM phase: ct = column group (4 cols), rt = row group (4 rows)
    int ct = tid % 24;
    int rt = tid / 24;

    float acc[4][4];
#pragma unroll
    for (int rr = 0; rr < 4; rr++)
#pragma unroll
        for (int cc = 0; cc < 4; cc++) acc[rr][cc] = 0.f;

#pragma unroll
    for (int k = 0; k < DD; k += 4) {
        float wreg[4][4];
#pragma unroll
        for (int kk = 0; kk < 4; kk++)
            *(float4*)(&wreg[kk][0]) = *(const float4*)(Ws + (k + kk) * DD + ct * 4);
#pragma unroll
        for (int rr = 0; rr < 4; rr++) {
            float mreg[4];
            *(float4*)mreg = *(const float4*)(Ms + (rt * 4 + rr) * DD + k);
#pragma unroll
            for (int kk = 0; kk < 4; kk++)
#pragma unroll
                for (int cc = 0; cc < 4; cc++)
                    acc[rr][cc] = fmaf(mreg[kk], wreg[kk][cc], acc[rr][cc]);
        }
    }

    float bb[4];
    *(float4*)bb = *(const float4*)(B + ct * 4);
#pragma unroll
    for (int rr = 0; rr < 4; rr++) {
        int row = row0 + rt * 4 + rr;
        if (row < NN) {
            float oo[4];
#pragma unroll
            for (int cc = 0; cc < 4; cc++)
                oo[cc] = fmaxf(acc[rr][cc] + bb[cc], 0.f);
            if (SCALE_OUT) {
                float ns = g_ns[row];   // pre-scale for the next layer's gather
#pragma unroll
                for (int cc = 0; cc < 4; cc++) oo[cc] *= ns;
            }
            *(float4*)(out + row * DD + ct * 4) = *(float4*)oo;
        }
    }
}

// ---------------- launch ------------------------------------------------------
extern "C" void kernel_launch(void* const* d_in, const int* in_sizes, int n_in,
                              void* d_out, int out_size) {
    const float* h   = (const float*)d_in[0];
    const void*  src = d_in[1];
    const void*  dst = d_in[2];
    const float* Wl[3] = { (const float*)d_in[3], (const float*)d_in[5], (const float*)d_in[7] };
    const float* Bl[3] = { (const float*)d_in[4], (const float*)d_in[6], (const float*)d_in[8] };

    k_init<<<(NN + 255) / 256, 256>>>(src, dst);
    k_deg<<<(NE + 255) / 256, 256>>>(src, dst);
    k_norm_scan<<<1, SCAN_T>>>();
    k_fill<<<(NE + 255) / 256, 256>>>(src, dst);

    int nblk = (NN + 31) / 32;
    // Ping-pong: input and output of each layer are disjoint (gather of one
    // block may run concurrently with the epilogue of another).
    k_layer<1, 1><<<nblk, 192>>>(h,   Wl[0], Bl[0], g_x);           // h   -> g_x (scaled)
    k_layer<0, 1><<<nblk, 192>>>(g_x, Wl[1], Bl[1], g_y);           // g_x -> g_y (scaled)
    k_layer<0, 0><<<nblk, 192>>>(g_y, Wl[2], Bl[2], (float*)d_out); // g_y -> out
}

// round 12
// speedup vs baseline: 1.1040x; 1.1040x over previous
#include <cuda_runtime.h>

// Problem constants (fixed by the reference)
#define NN 50000          // nodes
#define NE 800000         // edges
#define DD 96             // feature dim
#define D4 24             // DD / 4 (float4 groups)
#define NB 196            // ceil(NN / 256) scan blocks

// ---------------- scratch (device globals; no allocation allowed) ----------
__device__ float g_x[NN * DD];     // layer activations (pre-scaled by norm_src)
__device__ float g_m[NN * DD];     // aggregated messages (already * norm_dst)
__device__ int   g_od[NN];         // out degree (src side)
__device__ int   g_id[NN];         // in degree (dst side)
__device__ float g_ns[NN];         // out_deg^-1/2
__device__ float g_nd[NN];         // in_deg^-1/2
__device__ int   g_off[NN + 1];    // CSR offsets (by dst)
__device__ int   g_cur[NN];        // CSR fill cursors
__device__ int   g_eidx[NE];       // src ids grouped by dst
__device__ int   g_is64;           // 1 if index arrays are int64, 0 if int32
__device__ int   g_bsum[NB];       // per-block in-degree sums
__device__ int   g_boff[NB];       // exclusive scan of g_bsum

__device__ __forceinline__ int load_idx(const void* p, int e, int is64) {
    if (is64) return (int)((const long long*)p)[e];
    return ((const int*)p)[e];
}

// ---------------- init: zero degrees + dtype probe in block 0 ---------------
// int32 ids read as int64 pack two ids per word -> value >= 2^32 unless the
// high id is 0 (prob 1/50000 per sample; 256 samples -> certain detection).
__global__ void k_init(const void* src, const void* dst) {
    int i = blockIdx.x * blockDim.x + threadIdx.x;
    if (i < NN) { g_od[i] = 0; g_id[i] = 0; }
    if (blockIdx.x == 0) {
        __shared__ int bad;
        if (threadIdx.x == 0) bad = 0;
        __syncthreads();
        long long v1 = ((const long long*)src)[threadIdx.x];
        long long v2 = ((const long long*)dst)[threadIdx.x];
        if (v1 < 0 || v1 >= NN || v2 < 0 || v2 >= NN) bad = 1;
        __syncthreads();
        if (threadIdx.x == 0) g_is64 = bad ? 0 : 1;
    }
}

__global__ void k_deg(const void* __restrict__ src, const void* __restrict__ dst) {
    int e = blockIdx.x * blockDim.x + threadIdx.x;
    if (e < NE) {
        int is64 = g_is64;
        atomicAdd(&g_od[load_idx(src, e, is64)], 1);
        atomicAdd(&g_id[load_idx(dst, e, is64)], 1);
    }
}

// ---------------- norms + per-block in-degree sums (coalesced) --------------
__global__ void k_norm_bsum() {
    int i = blockIdx.x * blockDim.x + threadIdx.x;
    int lane = threadIdx.x & 31, w = threadIdx.x >> 5;
    int idg = 0;
    if (i < NN) {
        int odg = g_od[i];
        idg = g_id[i];
        g_ns[i] = rsqrtf((float)max(odg, 1));
        g_nd[i] = rsqrtf((float)max(idg, 1));
    }
    int s = idg;
#pragma unroll
    for (int o = 16; o > 0; o >>= 1) s += __shfl_down_sync(0xffffffffu, s, o);
    __shared__ int ws[8];
    if (lane == 0) ws[w] = s;
    __syncthreads();
    if (threadIdx.x == 0) {
        int tot = 0;
#pragma unroll
        for (int k = 0; k < 8; k++) tot += ws[k];
        g_bsum[blockIdx.x] = tot;
    }
}

// ---------------- scan the 196 block sums (single tiny block) ---------------
__global__ void k_scanb() {
    int t = threadIdx.x;                    // 256 threads
    int lane = t & 31, w = t >> 5;
    int v = (t < NB) ? g_bsum[t] : 0;
    int x = v;
#pragma unroll
    for (int o = 1; o < 32; o <<= 1) {
        int u = __shfl_up_sync(0xffffffffu, x, o);
        if (lane >= o) x += u;
    }
    __shared__ int ws[8];
    if (lane == 31) ws[w] = x;
    __syncthreads();
    if (w == 0 && lane < 8) {
        int y = ws[lane];
#pragma unroll
        for (int o = 1; o < 8; o <<= 1) {
            int u = __shfl_up_sync(0x000000ffu, y, o);
            if (lane >= o) y += u;
        }
        ws[lane] = y;
    }
    __syncthreads();
    int incl = x + (w > 0 ? ws[w - 1] : 0);
    if (t < NB) g_boff[t] = incl - v;       // exclusive
}

// ---------------- per-node CSR offsets (coalesced block scan) ----------------
__global__ void k_offsets() {
    int i = blockIdx.x * blockDim.x + threadIdx.x;
    int lane = threadIdx.x & 31, w = threadIdx.x >> 5;
    int v = (i < NN) ? g_id[i] : 0;
    int x = v;
#pragma unroll
    for (int o = 1; o < 32; o <<= 1) {
        int u = __shfl_up_sync(0xffffffffu, x, o);
        if (lane >= o) x += u;
    }
    __shared__ int ws[8];
    if (lane == 31) ws[w] = x;
    __syncthreads();
    if (w == 0 && lane < 8) {
        int y = ws[lane];
#pragma unroll
        for (int o = 1; o < 8; o <<= 1) {
            int u = __shfl_up_sync(0x000000ffu, y, o);
            if (lane >= o) y += u;
        }
        ws[lane] = y;
    }
    __syncthreads();
    int ex = x - v + (w > 0 ? ws[w - 1] : 0);
    int off = g_boff[blockIdx.x] + ex;
    if (i < NN) { g_off[i] = off; g_cur[i] = off; }
    if (i == NN - 1) g_off[NN] = off + v;   // == NE
}

__global__ void k_fill(const void* __restrict__ src, const void* __restrict__ dst) {
    int e = blockIdx.x * blockDim.x + threadIdx.x;
    if (e < NE) {
        int is64 = g_is64;
        int s = load_idx(src, e, is64);
        int d = load_idx(dst, e, is64);
        int pos = atomicAdd(&g_cur[d], 1);
        g_eidx[pos] = s;
    }
}

// ---------------- CSR gather: m[d] = nd[d] * sum_{e in CSR[d]} x[src[e]] -----
// One warp per dst node. Lanes batch-load 32 edge indices (coalesced), then
// shuffle-broadcast each src; lanes 0-23 each carry one float4 of the 96-wide
// feature row (one LDG.128 per edge instead of 3x LDG.32).
// SCALE_EDGE=1 (layer 0): X is raw h; scale each message by g_ns[src].
template <int SCALE_EDGE>
__global__ __launch_bounds__(256) void k_gather(const float* __restrict__ X) {
    int warp = (blockIdx.x * blockDim.x + threadIdx.x) >> 5;
    int lane = threadIdx.x & 31;
    if (warp >= NN) return;
    int beg = g_off[warp];
    int end = g_off[warp + 1];
    const float4* X4 = (const float4*)X;
    float4 acc = make_float4(0.f, 0.f, 0.f, 0.f);
    for (int base = beg; base < end; base += 32) {
        int got = min(32, end - base);
        int idx = (base + lane < end) ? g_eidx[base + lane] : 0;
        float nsv = 0.f;
        if (SCALE_EDGE) nsv = (base + lane < end) ? g_ns[idx] : 0.f;
        for (int j = 0; j < got; j++) {
            int s = __shfl_sync(0xffffffffu, idx, j);
            float f;
            if (SCALE_EDGE) f = __shfl_sync(0xffffffffu, nsv, j);
            if (lane < D4) {
                float4 v = X4[s * D4 + lane];
                if (SCALE_EDGE) {
                    acc.x = fmaf(v.x, f, acc.x);
                    acc.y = fmaf(v.y, f, acc.y);
                    acc.z = fmaf(v.z, f, acc.z);
                    acc.w = fmaf(v.w, f, acc.w);
                } else {
                    acc.x += v.x; acc.y += v.y; acc.z += v.z; acc.w += v.w;
                }
            }
        }
    }
    if (lane < D4) {
        float nd = g_nd[warp];
        acc.x *= nd; acc.y *= nd; acc.z *= nd; acc.w *= nd;
        ((float4*)(g_m + warp * DD))[lane] = acc;
    }
}

// ---------------- GEMM + bias + relu (+ fused norm_src pre-scale) -----------
// out[i][j] = relu(b[j] + sum_k m[i][k] * W[k][j]); SCALE_OUT=1 additionally
// multiplies by norm_src[i] (pre-scale for the next layer's gather).
// Block: 192 threads, 32-row tile. W (36KB) + M-tile (12KB) in smem (48KB).
template <int SCALE_OUT>
__global__ __launch_bounds__(192) void k_gemm(const float* __restrict__ W,
                                              const float* __restrict__ B,
                                              float* __restrict__ out) {
    __shared__ float Ws[DD * DD];   // 36864 B
    __shared__ float Ms[32 * DD];   // 12288 B
    int tid = threadIdx.x;
    int row0 = blockIdx.x * 32;

    const float4* W4 = (const float4*)W;
    float4* Ws4 = (float4*)Ws;
#pragma unroll
    for (int i = 0; i < 12; i++) Ws4[tid + i * 192] = W4[tid + i * 192];

#pragma unroll
    for (int i = 0; i < 4; i++) {
        int li = tid + i * 192;          // 0..767
        int r = li / D4;
        int c4 = li - r * D4;
        int row = row0 + r;
        float4 v = make_float4(0.f, 0.f, 0.f, 0.f);
        if (row < NN) v = ((const float4*)g_m)[row * D4 + c4];
        ((float4*)Ms)[li] = v;
    }
    __syncthreads();

    int ct = tid % 24;    // column group (4 cols)
    int rt = tid / 24;    // row group (4 rows)

    float acc[4][4];
#pragma unroll
    for (int rr = 0; rr < 4; rr++)
#pragma unroll
        for (int cc = 0; cc < 4; cc++) acc[rr][cc] = 0.f;

#pragma unroll
    for (int k = 0; k < DD; k += 4) {
        float wreg[4][4];
#pragma unroll
        for (int kk = 0; kk < 4; kk++)
            *(float4*)(&wreg[kk][0]) = *(const float4*)(Ws + (k + kk) * DD + ct * 4);
#pragma unroll
        for (int rr = 0; rr < 4; rr++) {
            float mreg[4];
            *(float4*)mreg = *(const float4*)(Ms + (rt * 4 + rr) * DD + k);
#pragma unroll
            for (int kk = 0; kk < 4; kk++)
#pragma unroll
                for (int cc = 0; cc < 4; cc++)
                    acc[rr][cc] = fmaf(mreg[kk], wreg[kk][cc], acc[rr][cc]);
        }
    }

    float bb[4];
    *(float4*)bb = *(const float4*)(B + ct * 4);
#pragma unroll
    for (int rr = 0; rr < 4; rr++) {
        int row = row0 + rt * 4 + rr;
        if (row < NN) {
            float oo[4];
#pragma unroll
            for (int cc = 0; cc < 4; cc++)
                oo[cc] = fmaxf(acc[rr][cc] + bb[cc], 0.f);
            if (SCALE_OUT) {
                float ns = g_ns[row];   // pre-scale for the next layer's gather
#pragma unroll
                for (int cc = 0; cc < 4; cc++) oo[cc] *= ns;
            }
            *(float4*)(out + row * DD + ct * 4) = *(float4*)oo;
        }
    }
}

// ---------------- launch ------------------------------------------------------
extern "C" void kernel_launch(void* const* d_in, const int* in_sizes, int n_in,
                              void* d_out, int out_size) {
    const float* h   = (const float*)d_in[0];
    const void*  src = d_in[1];
    const void*  dst = d_in[2];
    const float* Wl[3] = { (const float*)d_in[3], (const float*)d_in[5], (const float*)d_in[7] };
    const float* Bl[3] = { (const float*)d_in[4], (const float*)d_in[6], (const float*)d_in[8] };

    k_init<<<NB, 256>>>(src, dst);
    k_deg<<<(NE + 255) / 256, 256>>>(src, dst);
    k_norm_bsum<<<NB, 256>>>();
    k_scanb<<<1, 256>>>();
    k_offsets<<<NB, 256>>>();
    k_fill<<<(NE + 255) / 256, 256>>>(src, dst);

    int gblk = (NN * 32 + 255) / 256;   // one warp per node
    int mblk = (NN + 31) / 32;          // 32-row GEMM tiles
    // Layer 0: gather from raw h with per-edge norm_src; GEMM pre-scales output.
    k_gather<1><<<gblk, 256>>>(h);
    k_gemm<1><<<mblk, 192>>>(Wl[0], Bl[0], g_x);
    // Layer 1
    k_gather<0><<<gblk, 256>>>(g_x);
    k_gemm<1><<<mblk, 192>>>(Wl[1], Bl[1], g_x);
    // Layer 2
    k_gather<0><<<gblk, 256>>>(g_x);
    k_gemm<0><<<mblk, 192>>>(Wl[2], Bl[2], (float*)d_out);
}

// round 13
// speedup vs baseline: 1.1056x; 1.0014x over previous
#include <cuda_runtime.h>

// Problem constants (fixed by the reference)
#define NN 50000          // nodes
#define NE 800000         // edges
#define DD 96             // feature dim
#define D4 24             // DD / 4 (float4 groups)
#define NB 196            // ceil(NN / 256) scan blocks

// ---------------- scratch (device globals; no allocation allowed) ----------
__device__ float g_x[NN * DD];     // layer activations (pre-scaled by norm_src)
__device__ float g_m[NN * DD];     // aggregated messages (already * norm_dst)
__device__ int   g_od[NN];         // out degree (src side)
__device__ int   g_id[NN];         // in degree (dst side)
__device__ float g_ns[NN];         // out_deg^-1/2
__device__ float g_nd[NN];         // in_deg^-1/2
__device__ int   g_off[NN + 1];    // CSR offsets (by dst)
__device__ int   g_cur[NN];        // CSR fill cursors
__device__ int   g_eidx[NE];       // src ids grouped by dst
__device__ int   g_is64;           // 1 if index arrays are int64, 0 if int32
__device__ int   g_bsum[NB];       // per-block in-degree sums
__device__ int   g_boff[NB];       // exclusive scan of g_bsum

__device__ __forceinline__ int load_idx(const void* p, int e, int is64) {
    if (is64) return (int)((const long long*)p)[e];
    return ((const int*)p)[e];
}

// ---------------- init: zero degrees + dtype probe in block 0 ---------------
// int32 ids read as int64 pack two ids per word -> value >= 2^32 unless the
// high id is 0 (prob 1/50000 per sample; 256 samples -> certain detection).
__global__ void k_init(const void* src, const void* dst) {
    int i = blockIdx.x * blockDim.x + threadIdx.x;
    if (i < NN) { g_od[i] = 0; g_id[i] = 0; }
    if (blockIdx.x == 0) {
        __shared__ int bad;
        if (threadIdx.x == 0) bad = 0;
        __syncthreads();
        long long v1 = ((const long long*)src)[threadIdx.x];
        long long v2 = ((const long long*)dst)[threadIdx.x];
        if (v1 < 0 || v1 >= NN || v2 < 0 || v2 >= NN) bad = 1;
        __syncthreads();
        if (threadIdx.x == 0) g_is64 = bad ? 0 : 1;
    }
}

__global__ void k_deg(const void* __restrict__ src, const void* __restrict__ dst) {
    int e = blockIdx.x * blockDim.x + threadIdx.x;
    if (e < NE) {
        int is64 = g_is64;
        atomicAdd(&g_od[load_idx(src, e, is64)], 1);
        atomicAdd(&g_id[load_idx(dst, e, is64)], 1);
    }
}

// ---------------- norms + per-block in-degree sums (coalesced) --------------
__global__ void k_norm_bsum() {
    int i = blockIdx.x * blockDim.x + threadIdx.x;
    int lane = threadIdx.x & 31, w = threadIdx.x >> 5;
    int idg = 0;
    if (i < NN) {
        int odg = g_od[i];
        idg = g_id[i];
        g_ns[i] = rsqrtf((float)max(odg, 1));
        g_nd[i] = rsqrtf((float)max(idg, 1));
    }
    int s = idg;
#pragma unroll
    for (int o = 16; o > 0; o >>= 1) s += __shfl_down_sync(0xffffffffu, s, o);
    __shared__ int ws[8];
    if (lane == 0) ws[w] = s;
    __syncthreads();
    if (threadIdx.x == 0) {
        int tot = 0;
#pragma unroll
        for (int k = 0; k < 8; k++) tot += ws[k];
        g_bsum[blockIdx.x] = tot;
    }
}

// ---------------- scan the 196 block sums (single tiny block) ---------------
__global__ void k_scanb() {
    int t = threadIdx.x;                    // 256 threads
    int lane = t & 31, w = t >> 5;
    int v = (t < NB) ? g_bsum[t] : 0;
    int x = v;
#pragma unroll
    for (int o = 1; o < 32; o <<= 1) {
        int u = __shfl_up_sync(0xffffffffu, x, o);
        if (lane >= o) x += u;
    }
    __shared__ int ws[8];
    if (lane == 31) ws[w] = x;
    __syncthreads();
    if (w == 0 && lane < 8) {
        int y = ws[lane];
#pragma unroll
        for (int o = 1; o < 8; o <<= 1) {
            int u = __shfl_up_sync(0x000000ffu, y, o);
            if (lane >= o) y += u;
        }
        ws[lane] = y;
    }
    __syncthreads();
    int incl = x + (w > 0 ? ws[w - 1] : 0);
    if (t < NB) g_boff[t] = incl - v;       // exclusive
}

// ---------------- per-node CSR offsets (coalesced block scan) ----------------
__global__ void k_offsets() {
    int i = blockIdx.x * blockDim.x + threadIdx.x;
    int lane = threadIdx.x & 31, w = threadIdx.x >> 5;
    int v = (i < NN) ? g_id[i] : 0;
    int x = v;
#pragma unroll
    for (int o = 1; o < 32; o <<= 1) {
        int u = __shfl_up_sync(0xffffffffu, x, o);
        if (lane >= o) x += u;
    }
    __shared__ int ws[8];
    if (lane == 31) ws[w] = x;
    __syncthreads();
    if (w == 0 && lane < 8) {
        int y = ws[lane];
#pragma unroll
        for (int o = 1; o < 8; o <<= 1) {
            int u = __shfl_up_sync(0x000000ffu, y, o);
            if (lane >= o) y += u;
        }
        ws[lane] = y;
    }
    __syncthreads();
    int ex = x - v + (w > 0 ? ws[w - 1] : 0);
    int off = g_boff[blockIdx.x] + ex;
    if (i < NN) { g_off[i] = off; g_cur[i] = off; }
    if (i == NN - 1) g_off[NN] = off + v;   // == NE
}

__global__ void k_fill(const void* __restrict__ src, const void* __restrict__ dst) {
    int e = blockIdx.x * blockDim.x + threadIdx.x;
    if (e < NE) {
        int is64 = g_is64;
        int s = load_idx(src, e, is64);
        int d = load_idx(dst, e, is64);
        int pos = atomicAdd(&g_cur[d], 1);
        g_eidx[pos] = s;
    }
}

// ---------------- CSR gather: m[d] = nd[d] * sum_{e in CSR[d]} x[src[e]] -----
// One warp per dst node. Lanes batch-load 32 edge indices (coalesced), then
// shuffle-broadcast each src; lanes 0-23 each carry one float4 of the 96-wide
// feature row (one LDG.128 per edge instead of 3x LDG.32).
// SCALE_EDGE=1 (layer 0): X is raw h; scale each message by g_ns[src].
template <int SCALE_EDGE>
__global__ __launch_bounds__(256) void k_gather(const float* __restrict__ X) {
    int warp = (blockIdx.x * blockDim.x + threadIdx.x) >> 5;
    int lane = threadIdx.x & 31;
    if (warp >= NN) return;
    int beg = g_off[warp];
    int end = g_off[warp + 1];
    const float4* X4 = (const float4*)X;
    float4 acc = make_float4(0.f, 0.f, 0.f, 0.f);
    for (int base = beg; base < end; base += 32) {
        int got = min(32, end - base);
        int idx = (base + lane < end) ? g_eidx[base + lane] : 0;
        float nsv = 0.f;
        if (SCALE_EDGE) nsv = (base + lane < end) ? g_ns[idx] : 0.f;
        for (int j = 0; j < got; j++) {
            int s = __shfl_sync(0xffffffffu, idx, j);
            float f;
            if (SCALE_EDGE) f = __shfl_sync(0xffffffffu, nsv, j);
            if (lane < D4) {
                float4 v = X4[s * D4 + lane];
                if (SCALE_EDGE) {
                    acc.x = fmaf(v.x, f, acc.x);
                    acc.y = fmaf(v.y, f, acc.y);
                    acc.z = fmaf(v.z, f, acc.z);
                    acc.w = fmaf(v.w, f, acc.w);
                } else {
                    acc.x += v.x; acc.y += v.y; acc.z += v.z; acc.w += v.w;
                }
            }
        }
    }
    if (lane < D4) {
        float nd = g_nd[warp];
        acc.x *= nd; acc.y *= nd; acc.z *= nd; acc.w *= nd;
        ((float4*)(g_m + warp * DD))[lane] = acc;
    }
}

// ---------------- GEMM + bias + relu (+ fused norm_src pre-scale) -----------
// out[i][j] = relu(b[j] + sum_k m[i][k] * W[k][j]); SCALE_OUT=1 additionally
// multiplies by norm_src[i] (pre-scale for the next layer's gather).
// Block: 192 threads, 32-row tile. W (36KB) + M-tile (12KB) in smem (48KB).
template <int SCALE_OUT>
__global__ __launch_bounds__(192) void k_gemm(const float* __restrict__ W,
                                              const float* __restrict__ B,
                                              float* __restrict__ out) {
    __shared__ float Ws[DD * DD];   // 36864 B
    __shared__ float Ms[32 * DD];   // 12288 B
    int tid = threadIdx.x;
    int row0 = blockIdx.x * 32;

    const float4* W4 = (const float4*)W;
    float4* Ws4 = (float4*)Ws;
#pragma unroll
    for (int i = 0; i < 12; i++) Ws4[tid + i * 192] = W4[tid + i * 192];

#pragma unroll
    for (int i = 0; i < 4; i++) {
        int li = tid + i * 192;          // 0..767
        int r = li / D4;
        int c4 = li - r * D4;
        int row = row0 + r;
        float4 v = make_float4(0.f, 0.f, 0.f, 0.f);
        if (row < NN) v = ((const float4*)g_m)[row * D4 + c4];
        ((float4*)Ms)[li] = v;
    }
    __syncthreads();

    int ct = tid % 24;    // column group (4 cols)
    int rt = tid / 24;    // row group (4 rows)

    float acc[4][4];
#pragma unroll
    for (int rr = 0; rr < 4; rr++)
#pragma unroll
        for (int cc = 0; cc < 4; cc++) acc[rr][cc] = 0.f;

#pragma unroll
    for (int k = 0; k < DD; k += 4) {
        float wreg[4][4];
#pragma unroll
        for (int kk = 0; kk < 4; kk++)
            *(float4*)(&wreg[kk][0]) = *(const float4*)(Ws + (k + kk) * DD + ct * 4);
#pragma unroll
        for (int rr = 0; rr < 4; rr++) {
            float mreg[4];
            *(float4*)mreg = *(const float4*)(Ms + (rt * 4 + rr) * DD + k);
#pragma unroll
            for (int kk = 0; kk < 4; kk++)
#pragma unroll
                for (int cc = 0; cc < 4; cc++)
                    acc[rr][cc] = fmaf(mreg[kk], wreg[kk][cc], acc[rr][cc]);
        }
    }

    float bb[4];
    *(float4*)bb = *(const float4*)(B + ct * 4);
#pragma unroll
    for (int rr = 0; rr < 4; rr++) {
        int row = row0 + rt * 4 + rr;
        if (row < NN) {
            float oo[4];
#pragma unroll
            for (int cc = 0; cc < 4; cc++)
                oo[cc] = fmaxf(acc[rr][cc] + bb[cc], 0.f);
            if (SCALE_OUT) {
                float ns = g_ns[row];   // pre-scale for the next layer's gather
#pragma unroll
                for (int cc = 0; cc < 4; cc++) oo[cc] *= ns;
            }
            *(float4*)(out + row * DD + ct * 4) = *(float4*)oo;
        }
    }
}

// ---------------- launch ------------------------------------------------------
extern "C" void kernel_launch(void* const* d_in, const int* in_sizes, int n_in,
                              void* d_out, int out_size) {
    const float* h   = (const float*)d_in[0];
    const void*  src = d_in[1];
    const void*  dst = d_in[2];
    const float* Wl[3] = { (const float*)d_in[3], (const float*)d_in[5], (const float*)d_in[7] };
    const float* Bl[3] = { (const float*)d_in[4], (const float*)d_in[6], (const float*)d_in[8] };

    k_init<<<NB, 256>>>(src, dst);
    k_deg<<<(NE + 255) / 256, 256>>>(src, dst);
    k_norm_bsum<<<NB, 256>>>();
    k_scanb<<<1, 256>>>();
    k_offsets<<<NB, 256>>>();
    k_fill<<<(NE + 255) / 256, 256>>>(src, dst);

    int gblk = (NN * 32 + 255) / 256;   // one warp per node
    int mblk = (NN + 31) / 32;          // 32-row GEMM tiles
    // Layer 0: gather from raw h with per-edge norm_src; GEMM pre-scales output.
    k_gather<1><<<gblk, 256>>>(h);
    k_gemm<1><<<mblk, 192>>>(Wl[0], Bl[0], g_x);
    // Layer 1
    k_gather<0><<<gblk, 256>>>(g_x);
    k_gemm<1><<<mblk, 192>>>(Wl[1], Bl[1], g_x);
    // Layer 2
    k_gather<0><<<gblk, 256>>>(g_x);
    k_gemm<0><<<mblk, 192>>>(Wl[2], Bl[2], (float*)d_out);
}

// round 14
// speedup vs baseline: 20.2980x; 18.3600x over previous
#include <cuda_runtime.h>

// Problem constants (fixed by the reference)
#define NN 50000          // nodes
#define NE 800000         // edges
#define DD 96             // feature dim
#define D4 24             // DD / 4 (float4 groups)
#define NB 196            // ceil(NN / 256) scan blocks

// ---------------- scratch (device globals; no allocation allowed) -----------
// RULE (learned R10-R13): NEVER pass these symbols as kernel arguments from
// host code — the host-side shadow address is silently GPU-accessible via
// ATS/NVLink-C2C on GB300 and runs at host-memory speed (13x regression).
// Kernels reference them directly in device code.
__device__ float g_x[NN * DD];     // layer activations (pre-scaled by norm_src)
__device__ float g_m[NN * DD];     // aggregated messages (already * norm_dst)
__device__ int   g_od[NN];         // out degree (src side)
__device__ int   g_id[NN];         // in degree (dst side)
__device__ float g_ns[NN];         // out_deg^-1/2
__device__ float g_nd[NN];         // in_deg^-1/2
__device__ int   g_off[NN + 1];    // CSR offsets (by dst)
__device__ int   g_cur[NN];        // CSR fill cursors
__device__ int   g_eidx[NE];       // src ids grouped by dst
__device__ int   g_is64;           // 1 if index arrays are int64, 0 if int32
__device__ int   g_bsum[NB];       // per-block in-degree sums
__device__ int   g_boff[NB];       // exclusive scan of g_bsum

__device__ __forceinline__ int load_idx(const void* p, int e, int is64) {
    if (is64) return (int)((const long long*)p)[e];
    return ((const int*)p)[e];
}

// ---------------- init: zero degrees + dtype probe in block 0 ---------------
// int32 ids read as int64 pack two ids per word -> value >= 2^32 unless the
// high id is 0 (prob 1/50000 per sample; 256 samples -> certain detection).
__global__ void k_init(const void* src, const void* dst) {
    int i = blockIdx.x * blockDim.x + threadIdx.x;
    if (i < NN) { g_od[i] = 0; g_id[i] = 0; }
    if (blockIdx.x == 0) {
        __shared__ int bad;
        if (threadIdx.x == 0) bad = 0;
        __syncthreads();
        long long v1 = ((const long long*)src)[threadIdx.x];
        long long v2 = ((const long long*)dst)[threadIdx.x];
        if (v1 < 0 || v1 >= NN || v2 < 0 || v2 >= NN) bad = 1;
        __syncthreads();
        if (threadIdx.x == 0) g_is64 = bad ? 0 : 1;
    }
}

__global__ void k_deg(const void* __restrict__ src, const void* __restrict__ dst) {
    int e = blockIdx.x * blockDim.x + threadIdx.x;
    if (e < NE) {
        int is64 = g_is64;
        atomicAdd(&g_od[load_idx(src, e, is64)], 1);
        atomicAdd(&g_id[load_idx(dst, e, is64)], 1);
    }
}

// ---------------- norms + per-block in-degree sums (coalesced) --------------
__global__ void k_norm_bsum() {
    int i = blockIdx.x * blockDim.x + threadIdx.x;
    int lane = threadIdx.x & 31, w = threadIdx.x >> 5;
    int idg = 0;
    if (i < NN) {
        int odg = g_od[i];
        idg = g_id[i];
        g_ns[i] = rsqrtf((float)max(odg, 1));
        g_nd[i] = rsqrtf((float)max(idg, 1));
    }
    int s = idg;
#pragma unroll
    for (int o = 16; o > 0; o >>= 1) s += __shfl_down_sync(0xffffffffu, s, o);
    __shared__ int ws[8];
    if (lane == 0) ws[w] = s;
    __syncthreads();
    if (threadIdx.x == 0) {
        int tot = 0;
#pragma unroll
        for (int k = 0; k < 8; k++) tot += ws[k];
        g_bsum[blockIdx.x] = tot;
    }
}

// ---------------- scan the 196 block sums (single tiny block) ---------------
__global__ void k_scanb() {
    int t = threadIdx.x;                    // 256 threads
    int lane = t & 31, w = t >> 5;
    int v = (t < NB) ? g_bsum[t] : 0;
    int x = v;
#pragma unroll
    for (int o = 1; o < 32; o <<= 1) {
        int u = __shfl_up_sync(0xffffffffu, x, o);
        if (lane >= o) x += u;
    }
    __shared__ int ws[8];
    if (lane == 31) ws[w] = x;
    __syncthreads();
    if (w == 0 && lane < 8) {
        int y = ws[lane];
#pragma unroll
        for (int o = 1; o < 8; o <<= 1) {
            int u = __shfl_up_sync(0x000000ffu, y, o);
            if (lane >= o) y += u;
        }
        ws[lane] = y;
    }
    __syncthreads();
    int incl = x + (w > 0 ? ws[w - 1] : 0);
    if (t < NB) g_boff[t] = incl - v;       // exclusive
}

// ---------------- per-node CSR offsets (coalesced block scan) ----------------
__global__ void k_offsets() {
    int i = blockIdx.x * blockDim.x + threadIdx.x;
    int lane = threadIdx.x & 31, w = threadIdx.x >> 5;
    int v = (i < NN) ? g_id[i] : 0;
    int x = v;
#pragma unroll
    for (int o = 1; o < 32; o <<= 1) {
        int u = __shfl_up_sync(0xffffffffu, x, o);
        if (lane >= o) x += u;
    }
    __shared__ int ws[8];
    if (lane == 31) ws[w] = x;
    __syncthreads();
    if (w == 0 && lane < 8) {
        int y = ws[lane];
#pragma unroll
        for (int o = 1; o < 8; o <<= 1) {
            int u = __shfl_up_sync(0x000000ffu, y, o);
            if (lane >= o) y += u;
        }
        ws[lane] = y;
    }
    __syncthreads();
    int ex = x - v + (w > 0 ? ws[w - 1] : 0);
    int off = g_boff[blockIdx.x] + ex;
    if (i < NN) { g_off[i] = off; g_cur[i] = off; }
    if (i == NN - 1) g_off[NN] = off + v;   // == NE
}

__global__ void k_fill(const void* __restrict__ src, const void* __restrict__ dst) {
    int e = blockIdx.x * blockDim.x + threadIdx.x;
    if (e < NE) {
        int is64 = g_is64;
        int s = load_idx(src, e, is64);
        int d = load_idx(dst, e, is64);
        int pos = atomicAdd(&g_cur[d], 1);
        g_eidx[pos] = s;
    }
}

// ---------------- CSR gather: m[d] = nd[d] * sum_{e in CSR[d]} x[src[e]] -----
// One warp per dst node. Lanes batch-load 32 edge indices (coalesced), then
// shuffle-broadcast each src; each lane accumulates 3 features (lane, +32, +64).
// USE_H=1 (layer 0): read the external h pointer and scale each message by
// g_ns[src] (per-edge). USE_H=0: read the internal, pre-scaled g_x.
template <int USE_H>
__global__ __launch_bounds__(256) void k_gather(const float* __restrict__ hext) {
    int warp = (blockIdx.x * blockDim.x + threadIdx.x) >> 5;
    int lane = threadIdx.x & 31;
    if (warp >= NN) return;
    const float* __restrict__ X = USE_H ? hext : g_x;   // device-side selection
    int beg = g_off[warp];
    int end = g_off[warp + 1];
    float a0 = 0.f, a1 = 0.f, a2 = 0.f;
    for (int base = beg; base < end; base += 32) {
        int got = min(32, end - base);
        int idx = (base + lane < end) ? g_eidx[base + lane] : 0;
        float nsv = 0.f;
        if (USE_H) nsv = (base + lane < end) ? g_ns[idx] : 0.f;
#pragma unroll 4
        for (int j = 0; j < got; j++) {
            int s = __shfl_sync(0xffffffffu, idx, j);
            const float* xp = X + s * DD;
            if (USE_H) {
                float f = __shfl_sync(0xffffffffu, nsv, j);
                a0 = fmaf(xp[lane],      f, a0);
                a1 = fmaf(xp[lane + 32], f, a1);
                a2 = fmaf(xp[lane + 64], f, a2);
            } else {
                a0 += xp[lane];
                a1 += xp[lane + 32];
                a2 += xp[lane + 64];
            }
        }
    }
    float nd = g_nd[warp];
    float* mp = g_m + warp * DD;
    mp[lane]      = a0 * nd;
    mp[lane + 32] = a1 * nd;
    mp[lane + 64] = a2 * nd;
}

// ---------------- GEMM + bias + relu (+ fused norm_src pre-scale) -----------
// out[i][j] = relu(b[j] + sum_k m[i][k] * W[k][j]).
// out != nullptr (last layer): write external buffer, no pre-scale.
// out == nullptr: write internal g_x, multiplied by norm_src[i] (pre-scale
// for the next layer's gather). Never pass g_x from host!
__global__ __launch_bounds__(192) void k_gemm(const float* __restrict__ W,
                                              const float* __restrict__ B,
                                              float* __restrict__ out) {
    __shared__ float Ws[DD * DD];   // 36864 B
    __shared__ float Ms[32 * DD];   // 12288 B
    int tid = threadIdx.x;
    int row0 = blockIdx.x * 32;

    const float4* W4 = (const float4*)W;
    float4* Ws4 = (float4*)Ws;
#pragma unroll
    for (int i = 0; i < 12; i++) Ws4[tid + i * 192] = W4[tid + i * 192];

#pragma unroll
    for (int i = 0; i < 4; i++) {
        int li = tid + i * 192;          // 0..767
        int r = li / D4;
        int c4 = li - r * D4;
        int row = row0 + r;
        float4 v = make_float4(0.f, 0.f, 0.f, 0.f);
        if (row < NN) v = ((const float4*)g_m)[row * D4 + c4];
        ((float4*)Ms)[li] = v;
    }
    __syncthreads();

    int ct = tid % 24;    // column group (4 cols)
    int rt = tid / 24;    // row group (4 rows)

    float acc[4][4];
#pragma unroll
    for (int rr = 0; rr < 4; rr++)
#pragma unroll
        for (int cc = 0; cc < 4; cc++) acc[rr][cc] = 0.f;

#pragma unroll
    for (int k = 0; k < DD; k += 4) {
        float wreg[4][4];
#pragma unroll
        for (int kk = 0; kk < 4; kk++)
            *(float4*)(&wreg[kk][0]) = *(const float4*)(Ws + (k + kk) * DD + ct * 4);
#pragma unroll
        for (int rr = 0; rr < 4; rr++) {
            float mreg[4];
            *(float4*)mreg = *(const float4*)(Ms + (rt * 4 + rr) * DD + k);
#pragma unroll
            for (int kk = 0; kk < 4; kk++)
#pragma unroll
                for (int cc = 0; cc < 4; cc++)
                    acc[rr][cc] = fmaf(mreg[kk], wreg[kk][cc], acc[rr][cc]);
        }
    }

    float bb[4];
    *(float4*)bb = *(const float4*)(B + ct * 4);
#pragma unroll
    for (int rr = 0; rr < 4; rr++) {
        int row = row0 + rt * 4 + rr;
        if (row < NN) {
            float oo[4];
#pragma unroll
            for (int cc = 0; cc < 4; cc++)
                oo[cc] = fmaxf(acc[rr][cc] + bb[cc], 0.f);
            if (out) {
                *(float4*)(out + row * DD + ct * 4) = *(float4*)oo;
            } else {
                float ns = g_ns[row];   // pre-scale for the next layer's gather
#pragma unroll
                for (int cc = 0; cc < 4; cc++) oo[cc] *= ns;
                *(float4*)(g_x + row * DD + ct * 4) = *(float4*)oo;
            }
        }
    }
}

// ---------------- launch ------------------------------------------------------
extern "C" void kernel_launch(void* const* d_in, const int* in_sizes, int n_in,
                              void* d_out, int out_size) {
    const float* h   = (const float*)d_in[0];
    const void*  src = d_in[1];
    const void*  dst = d_in[2];
    const float* Wl[3] = { (const float*)d_in[3], (const float*)d_in[5], (const float*)d_in[7] };
    const float* Bl[3] = { (const float*)d_in[4], (const float*)d_in[6], (const float*)d_in[8] };

    k_init<<<NB, 256>>>(src, dst);
    k_deg<<<(NE + 255) / 256, 256>>>(src, dst);
    k_norm_bsum<<<NB, 256>>>();
    k_scanb<<<1, 256>>>();
    k_offsets<<<NB, 256>>>();
    k_fill<<<(NE + 255) / 256, 256>>>(src, dst);

    int gblk = (NN * 32 + 255) / 256;   // one warp per node
    int mblk = (NN + 31) / 32;          // 32-row GEMM tiles
    // Layer 0: gather raw h with per-edge norm_src; GEMM pre-scales its output.
    k_gather<1><<<gblk, 256>>>(h);
    k_gemm<<<mblk, 192>>>(Wl[0], Bl[0], nullptr);
    // Layer 1 (internal g_x -> internal g_x; safe: gather/gemm are separate launches)
    k_gather<0><<<gblk, 256>>>(nullptr);
    k_gemm<<<mblk, 192>>>(Wl[1], Bl[1], nullptr);
    // Layer 2 -> external output
    k_gather<0><<<gblk, 256>>>(nullptr);
    k_gemm<<<mblk, 192>>>(Wl[2], Bl[2], (float*)d_out);
}